// round 7
// baseline (speedup 1.0000x reference)
#include <cuda_runtime.h>
#include <cstdint>

#define B_    8
#define P_    96
#define D_    128
#define H_    256
#define NPTS  (B_*P_)          // 768
#define NPAIR (B_*P_*P_)       // 73728
#define K3    (3*H_)           // 768

// ---------------- device scratch ----------------
__device__ __align__(16) float g_Wcat[K3*H_];          // fused (W2@Wf), tf32-rounded
__device__ __align__(16) float g_bias[H_];
__device__ __align__(16) float g_As[NPTS*H_];
__device__ __align__(16) float g_Bs[NPTS*H_];
__device__ __align__(16) float g_At[NPTS*H_];
__device__ __align__(16) float g_Bt[NPTS*H_];
__device__ __align__(16) float g_Ci[NPTS*H_];
__device__ __align__(16) float g_Hi[(size_t)NPAIR*H_]; // relu'd interaction hidden, tf32, 75.5MB

__device__ __forceinline__ float f2tf32(float x) {
    uint32_t r;
    asm("cvt.rna.tf32.f32 %0, %1;" : "=r"(r) : "f"(x));
    return __uint_as_float(r);
}

// ---------------- kernel A: fuse layer-2 weights with final projection ------
__global__ void __launch_bounds__(256) prep_weights(
    const float* __restrict__ Ws2, const float* __restrict__ Wt2,
    const float* __restrict__ Wi2, const float* __restrict__ Wf,
    const float* __restrict__ bs2, const float* __restrict__ bt2,
    const float* __restrict__ bi2, const float* __restrict__ bff)
{
    int r = blockIdx.x;
    int h = threadIdx.x;
    int p = r >> 8;
    int k = r & 255;
    const float* W2  = (p == 0) ? Ws2 : ((p == 1) ? Wt2 : Wi2);
    const float* Wfp = Wf + p * H_ * H_;
    float acc = 0.f;
    #pragma unroll 4
    for (int m = 0; m < H_; m++)
        acc = fmaf(W2[k*H_ + m], Wfp[m*H_ + h], acc);
    g_Wcat[r*H_ + h] = f2tf32(acc);

    if (r == 0) {
        float b = bff[h];
        for (int m = 0; m < H_; m++) {
            b = fmaf(bs2[m], Wf[m*H_ + h],          b);
            b = fmaf(bt2[m], Wf[(H_   + m)*H_ + h], b);
            b = fmaf(bi2[m], Wf[(2*H_ + m)*H_ + h], b);
        }
        g_bias[h] = b;
    }
}

// ---------------- kernel B: per-point projections ----------------
__global__ void __launch_bounds__(256) proj_points(
    const float* __restrict__ F,   const float* __restrict__ Ws1,
    const float* __restrict__ Wt1, const float* __restrict__ Wi1,
    const float* __restrict__ bs1, const float* __restrict__ bt1)
{
    __shared__ __align__(16) float sF[8][D_];
    int p0 = blockIdx.x * 8;
    int h  = threadIdx.x;
    for (int t = h; t < 8*D_; t += 256) sF[t / D_][t % D_] = F[p0*D_ + t];
    __syncthreads();

    float as[8], bs[8], at[8], bt[8], ci[8];
    float b1 = bs1[h], b2 = bt1[h];
    #pragma unroll
    for (int r = 0; r < 8; r++) { as[r]=b1; bs[r]=0.f; at[r]=b2; bt[r]=0.f; ci[r]=0.f; }

    for (int d = 0; d < D_; d++) {
        float wsa = Ws1[d*H_ + h];
        float wsb = Ws1[(D_ + d)*H_ + h];
        float wta = Wt1[d*H_ + h];
        float wtb = Wt1[(D_ + d)*H_ + h];
        float wib = Wi1[(D_ + d)*H_ + h];
        #pragma unroll
        for (int r = 0; r < 8; r++) {
            float f = sF[r][d];
            as[r] = fmaf(f, wsa, as[r]);
            bs[r] = fmaf(f, wsb, bs[r]);
            at[r] = fmaf(f, wta, at[r]);
            bt[r] = fmaf(f, wtb, bt[r]);
            ci[r] = fmaf(f, wib, ci[r]);
        }
    }
    #pragma unroll
    for (int r = 0; r < 8; r++) {
        int idx = (p0 + r)*H_ + h;
        g_As[idx]=as[r]; g_Bs[idx]=bs[r]; g_At[idx]=at[r]; g_Bt[idx]=bt[r]; g_Ci[idx]=ci[r];
    }
}

// ---------------- kernel C: interaction hidden via tf32 tensor cores --------
// CTA = (b,i). Hi[j,h] = relu( (f_i .* f_j) @ Wi1a + Ci[i,h] + Ci[j,h] + bi1[h] )
__global__ void __launch_bounds__(384) bilinear_hi(
    const float* __restrict__ F, const float* __restrict__ Wi1,
    const float* __restrict__ bi1)
{
    __shared__ __align__(16) float sP[16][96 + 8];
    __shared__ __align__(16) float sW[16][256 + 8];
    __shared__ float sFi[D_], sCii[H_], sBi1[H_];

    int bi = blockIdx.x;
    int b  = bi / P_;
    int tid  = threadIdx.x;
    int warp = tid >> 5, lane = tid & 31;
    int wm = warp >> 2, wn = warp & 3;
    int grp = lane >> 2, thr = lane & 3;

    for (int t = tid; t < D_; t += 384) sFi[t] = F[bi*D_ + t];
    for (int t = tid; t < H_; t += 384) { sCii[t] = g_Ci[bi*H_ + t]; sBi1[t] = bi1[t]; }
    __syncthreads();

    int j_a = tid >> 2, k_a = (tid & 3) << 2;
    const float* rowF = F + (b*P_ + j_a) * D_;

    float acc[2][8][4];
    #pragma unroll
    for (int mt = 0; mt < 2; mt++)
        #pragma unroll
        for (int nt = 0; nt < 8; nt++)
            #pragma unroll
            for (int c = 0; c < 4; c++) acc[mt][nt][c] = 0.f;

    for (int d0 = 0; d0 < D_; d0 += 16) {
        if (d0) __syncthreads();
        float4 v = *(const float4*)(rowF + d0 + k_a);
        sP[k_a+0][j_a] = f2tf32(sFi[d0+k_a+0] * v.x);
        sP[k_a+1][j_a] = f2tf32(sFi[d0+k_a+1] * v.y);
        sP[k_a+2][j_a] = f2tf32(sFi[d0+k_a+2] * v.z);
        sP[k_a+3][j_a] = f2tf32(sFi[d0+k_a+3] * v.w);
        for (int idx = tid; idx < 16*64; idx += 384) {
            int k = idx >> 6, n4 = (idx & 63) << 2;
            float4 w = *(const float4*)(&Wi1[(d0 + k)*H_ + n4]);
            w.x = f2tf32(w.x); w.y = f2tf32(w.y); w.z = f2tf32(w.z); w.w = f2tf32(w.w);
            *(float4*)&sW[k][n4] = w;
        }
        __syncthreads();

        #pragma unroll
        for (int ks = 0; ks < 2; ks++) {
            int kb = ks * 8;
            uint32_t af[2][4], bf[8][2];
            #pragma unroll
            for (int mt = 0; mt < 2; mt++) {
                int row = wm*32 + mt*16 + grp;
                af[mt][0] = __float_as_uint(sP[kb + thr    ][row]);
                af[mt][1] = __float_as_uint(sP[kb + thr    ][row + 8]);
                af[mt][2] = __float_as_uint(sP[kb + thr + 4][row]);
                af[mt][3] = __float_as_uint(sP[kb + thr + 4][row + 8]);
            }
            #pragma unroll
            for (int nt = 0; nt < 8; nt++) {
                int col = wn*64 + nt*8 + grp;
                bf[nt][0] = __float_as_uint(sW[kb + thr    ][col]);
                bf[nt][1] = __float_as_uint(sW[kb + thr + 4][col]);
            }
            #pragma unroll
            for (int mt = 0; mt < 2; mt++)
                #pragma unroll
                for (int nt = 0; nt < 8; nt++)
                    asm volatile(
                        "mma.sync.aligned.m16n8k8.row.col.f32.tf32.tf32.f32 "
                        "{%0,%1,%2,%3}, {%4,%5,%6,%7}, {%8,%9}, {%0,%1,%2,%3};"
                        : "+f"(acc[mt][nt][0]), "+f"(acc[mt][nt][1]),
                          "+f"(acc[mt][nt][2]), "+f"(acc[mt][nt][3])
                        : "r"(af[mt][0]), "r"(af[mt][1]), "r"(af[mt][2]), "r"(af[mt][3]),
                          "r"(bf[nt][0]), "r"(bf[nt][1]));
        }
    }

    #pragma unroll
    for (int mt = 0; mt < 2; mt++) {
        #pragma unroll
        for (int half = 0; half < 2; half++) {
            int j = wm*32 + mt*16 + grp + half*8;
            const float* cij = g_Ci + (b*P_ + j)*H_;
            size_t obase = ((size_t)bi*P_ + j)*H_;
            #pragma unroll
            for (int nt = 0; nt < 8; nt++) {
                int col = wn*64 + nt*8 + thr*2;
                float2 v;
                v.x = f2tf32(fmaxf(acc[mt][nt][half*2+0] + sCii[col]   + cij[col]   + sBi1[col],   0.f));
                v.y = f2tf32(fmaxf(acc[mt][nt][half*2+1] + sCii[col+1] + cij[col+1] + sBi1[col+1], 0.f));
                *(float2*)&g_Hi[obase + col] = v;
            }
        }
    }
}

// ---------------- kernel D: fused GEMM, full N=256 per CTA ------------------
// CTA = (b,i). out[j,n] = sum_k relu(H[j,k]) * Wcat[k,n] + bias, * mask.
// M=96, N=256, K=768. 384 threads, 12 warps = 3(m) x 4(n), warp tile 32x64.
__global__ void __launch_bounds__(384) gemm_fused(
    const float* __restrict__ dist, const float* __restrict__ mask,
    const float* __restrict__ Ws1,  float* __restrict__ out)
{
    __shared__ __align__(16) float sA[16][96 + 8];      // stride 104
    __shared__ __align__(16) float sB[16][256 + 8];     // stride 264
    __shared__ float sAsi[H_], sAti[H_], sW1c[H_];

    int bi = blockIdx.x;
    int b  = bi / P_;
    int tid  = threadIdx.x;
    int warp = tid >> 5, lane = tid & 31;
    int wm = warp >> 2, wn = warp & 3;      // 3 x 4
    int grp = lane >> 2, thr = lane & 3;

    for (int t = tid; t < H_; t += 384) {
        sAsi[t] = g_As[bi*H_ + t];
        sAti[t] = g_At[bi*H_ + t];
        sW1c[t] = Ws1[2*D_*H_ + t];        // Ws1 row 256 (distance)
    }
    __syncthreads();

    int j_a = tid >> 2, k_a = (tid & 3) << 2;
    const float* rowBs = g_Bs + (b*P_ + j_a)*H_;
    const float* rowBt = g_Bt + (b*P_ + j_a)*H_;
    const float* rowHi = g_Hi + ((size_t)bi*P_ + j_a)*H_;
    float dj = dist[bi*P_ + j_a];

    // sB loaders: 16 x 256 floats = 1024 float4 over 384 threads -> 3 slots
    int sb_k[3], sb_n[3];
    bool sb_p[3];
    #pragma unroll
    for (int s = 0; s < 3; s++) {
        int idx = s*384 + tid;
        sb_p[s] = idx < 1024;
        sb_k[s] = idx >> 6;
        sb_n[s] = (idx & 63) << 2;
    }

    float acc[2][8][4];
    #pragma unroll
    for (int mt = 0; mt < 2; mt++)
        #pragma unroll
        for (int nt = 0; nt < 8; nt++)
            #pragma unroll
            for (int c = 0; c < 4; c++) acc[mt][nt][c] = 0.f;

    // prologue prefetch (k0 = 0, phase S)
    float4 va = *(const float4*)(rowBs + k_a);
    float4 vb[3];
    #pragma unroll
    for (int s = 0; s < 3; s++)
        if (sb_p[s]) vb[s] = *(const float4*)(&g_Wcat[sb_k[s]*H_ + sb_n[s]]);

    for (int k0 = 0; k0 < K3; k0 += 16) {
        // build A tile
        float4 a;
        if (k0 < 256) {
            int kk = k0 + k_a;
            a.x = f2tf32(fmaxf(sAsi[kk+0] + va.x + dj*sW1c[kk+0], 0.f));
            a.y = f2tf32(fmaxf(sAsi[kk+1] + va.y + dj*sW1c[kk+1], 0.f));
            a.z = f2tf32(fmaxf(sAsi[kk+2] + va.z + dj*sW1c[kk+2], 0.f));
            a.w = f2tf32(fmaxf(sAsi[kk+3] + va.w + dj*sW1c[kk+3], 0.f));
        } else if (k0 < 512) {
            int kk = k0 - 256 + k_a;
            a.x = f2tf32(fmaxf(sAti[kk+0] + va.x, 0.f));
            a.y = f2tf32(fmaxf(sAti[kk+1] + va.y, 0.f));
            a.z = f2tf32(fmaxf(sAti[kk+2] + va.z, 0.f));
            a.w = f2tf32(fmaxf(sAti[kk+3] + va.w, 0.f));
        } else {
            a = va;   // g_Hi already relu'd + tf32-rounded
        }
        sA[k_a+0][j_a] = a.x; sA[k_a+1][j_a] = a.y;
        sA[k_a+2][j_a] = a.z; sA[k_a+3][j_a] = a.w;
        #pragma unroll
        for (int s = 0; s < 3; s++)
            if (sb_p[s]) *(float4*)&sB[sb_k[s]][sb_n[s]] = vb[s];
        __syncthreads();

        // prefetch next stage while mma runs
        int kn = k0 + 16;
        if (kn < K3) {
            const float* src = (kn < 256) ? (rowBs + kn)
                             : (kn < 512) ? (rowBt + (kn - 256))
                                          : (rowHi + (kn - 512));
            va = *(const float4*)(src + k_a);
            #pragma unroll
            for (int s = 0; s < 3; s++)
                if (sb_p[s]) vb[s] = *(const float4*)(&g_Wcat[(kn + sb_k[s])*H_ + sb_n[s]]);
        }

        #pragma unroll
        for (int ks = 0; ks < 2; ks++) {
            int kb = ks * 8;
            uint32_t af[2][4], bf[8][2];
            #pragma unroll
            for (int mt = 0; mt < 2; mt++) {
                int row = wm*32 + mt*16 + grp;
                af[mt][0] = __float_as_uint(sA[kb + thr    ][row]);
                af[mt][1] = __float_as_uint(sA[kb + thr    ][row + 8]);
                af[mt][2] = __float_as_uint(sA[kb + thr + 4][row]);
                af[mt][3] = __float_as_uint(sA[kb + thr + 4][row + 8]);
            }
            #pragma unroll
            for (int nt = 0; nt < 8; nt++) {
                int col = wn*64 + nt*8 + grp;
                bf[nt][0] = __float_as_uint(sB[kb + thr    ][col]);
                bf[nt][1] = __float_as_uint(sB[kb + thr + 4][col]);
            }
            #pragma unroll
            for (int mt = 0; mt < 2; mt++)
                #pragma unroll
                for (int nt = 0; nt < 8; nt++)
                    asm volatile(
                        "mma.sync.aligned.m16n8k8.row.col.f32.tf32.tf32.f32 "
                        "{%0,%1,%2,%3}, {%4,%5,%6,%7}, {%8,%9}, {%0,%1,%2,%3};"
                        : "+f"(acc[mt][nt][0]), "+f"(acc[mt][nt][1]),
                          "+f"(acc[mt][nt][2]), "+f"(acc[mt][nt][3])
                        : "r"(af[mt][0]), "r"(af[mt][1]), "r"(af[mt][2]), "r"(af[mt][3]),
                          "r"(bf[nt][0]), "r"(bf[nt][1]));
        }
        __syncthreads();
    }

    // epilogue
    float mi = mask[bi];
    #pragma unroll
    for (int mt = 0; mt < 2; mt++) {
        #pragma unroll
        for (int half = 0; half < 2; half++) {
            int j = wm*32 + mt*16 + grp + half*8;
            float mp = mi * mask[b*P_ + j];
            size_t obase = ((size_t)bi*P_ + j)*H_;
            #pragma unroll
            for (int nt = 0; nt < 8; nt++) {
                int col = wn*64 + nt*8 + thr*2;
                float2 v;
                v.x = (acc[mt][nt][half*2+0] + g_bias[col])     * mp;
                v.y = (acc[mt][nt][half*2+1] + g_bias[col + 1]) * mp;
                *(float2*)&out[obase + col] = v;
            }
        }
    }
}

// ---------------- launch --------------------------------------------------
extern "C" void kernel_launch(void* const* d_in, const int* in_sizes, int n_in,
                              void* d_out, int out_size)
{
    const float* F    = (const float*)d_in[0];
    const float* dist = (const float*)d_in[1];
    const float* mask = (const float*)d_in[2];
    const float* Ws1  = (const float*)d_in[3];
    const float* bs1  = (const float*)d_in[4];
    const float* Ws2  = (const float*)d_in[5];
    const float* bs2  = (const float*)d_in[6];
    const float* Wt1  = (const float*)d_in[7];
    const float* bt1  = (const float*)d_in[8];
    const float* Wt2  = (const float*)d_in[9];
    const float* bt2  = (const float*)d_in[10];
    const float* Wi1  = (const float*)d_in[11];
    const float* bi1  = (const float*)d_in[12];
    const float* Wi2  = (const float*)d_in[13];
    const float* bi2  = (const float*)d_in[14];
    const float* Wf   = (const float*)d_in[15];
    const float* bff  = (const float*)d_in[16];
    float* out = (float*)d_out;

    prep_weights<<<K3, 256>>>(Ws2, Wt2, Wi2, Wf, bs2, bt2, bi2, bff);
    proj_points<<<NPTS/8, 256>>>(F, Ws1, Wt1, Wi1, bs1, bt1);
    bilinear_hi<<<NPTS, 384>>>(F, Wi1, bi1);
    gemm_fused<<<NPTS, 384>>>(dist, mask, Ws1, out);
}

// round 9
// speedup vs baseline: 1.1527x; 1.1527x over previous
#include <cuda_runtime.h>
#include <cstdint>

#define B_    8
#define P_    96
#define D_    128
#define H_    256
#define NPTS  (B_*P_)          // 768
#define NPAIR (B_*P_*P_)       // 73728
#define K3    (3*H_)           // 768

// ---------------- device scratch ----------------
__device__ __align__(16) float g_Wcat[K3*H_];          // fused (W2@Wf), tf32-rounded
__device__ __align__(16) float g_bias[H_];
__device__ __align__(16) float g_Wi1t[D_*H_];          // Wi1 product-half, tf32-rounded
__device__ __align__(16) float g_As[NPTS*H_];
__device__ __align__(16) float g_Bs[NPTS*H_];
__device__ __align__(16) float g_At[NPTS*H_];
__device__ __align__(16) float g_Bt[NPTS*H_];
__device__ __align__(16) float g_Ci[NPTS*H_];
__device__ __align__(16) float g_Hi[(size_t)NPAIR*H_]; // relu'd interaction hidden, tf32, 75.5MB

__device__ __forceinline__ float f2tf32(float x) {
    uint32_t r;
    asm("cvt.rna.tf32.f32 %0, %1;" : "=r"(r) : "f"(x));
    return __uint_as_float(r);
}

// ---------------- kernel A: fuse layer-2 weights with final projection ------
__global__ void __launch_bounds__(256) prep_weights(
    const float* __restrict__ Ws2, const float* __restrict__ Wt2,
    const float* __restrict__ Wi2, const float* __restrict__ Wf,
    const float* __restrict__ bs2, const float* __restrict__ bt2,
    const float* __restrict__ bi2, const float* __restrict__ bff)
{
    int r = blockIdx.x;
    int h = threadIdx.x;
    int p = r >> 8;
    int k = r & 255;
    const float* W2  = (p == 0) ? Ws2 : ((p == 1) ? Wt2 : Wi2);
    const float* Wfp = Wf + p * H_ * H_;
    float acc = 0.f;
    #pragma unroll 4
    for (int m = 0; m < H_; m++)
        acc = fmaf(W2[k*H_ + m], Wfp[m*H_ + h], acc);
    g_Wcat[r*H_ + h] = f2tf32(acc);

    if (r == 0) {
        float b = bff[h];
        for (int m = 0; m < H_; m++) {
            b = fmaf(bs2[m], Wf[m*H_ + h],          b);
            b = fmaf(bt2[m], Wf[(H_   + m)*H_ + h], b);
            b = fmaf(bi2[m], Wf[(2*H_ + m)*H_ + h], b);
        }
        g_bias[h] = b;
    }
}

// ---------------- kernel A2: pre-round Wi1 product-half to tf32 -------------
__global__ void __launch_bounds__(256) prep_wi1(const float* __restrict__ Wi1)
{
    int d = blockIdx.x;            // 0..127
    int h = threadIdx.x;           // 0..255
    g_Wi1t[d*H_ + h] = f2tf32(Wi1[d*H_ + h]);
}

// ---------------- kernel B: per-point projections ----------------
__global__ void __launch_bounds__(256) proj_points(
    const float* __restrict__ F,   const float* __restrict__ Ws1,
    const float* __restrict__ Wt1, const float* __restrict__ Wi1,
    const float* __restrict__ bs1, const float* __restrict__ bt1)
{
    __shared__ __align__(16) float sF[8][D_];
    int p0 = blockIdx.x * 8;
    int h  = threadIdx.x;
    for (int t = h; t < 8*D_; t += 256) sF[t / D_][t % D_] = F[p0*D_ + t];
    __syncthreads();

    float as[8], bs[8], at[8], bt[8], ci[8];
    float b1 = bs1[h], b2 = bt1[h];
    #pragma unroll
    for (int r = 0; r < 8; r++) { as[r]=b1; bs[r]=0.f; at[r]=b2; bt[r]=0.f; ci[r]=0.f; }

    for (int d = 0; d < D_; d++) {
        float wsa = Ws1[d*H_ + h];
        float wsb = Ws1[(D_ + d)*H_ + h];
        float wta = Wt1[d*H_ + h];
        float wtb = Wt1[(D_ + d)*H_ + h];
        float wib = Wi1[(D_ + d)*H_ + h];
        #pragma unroll
        for (int r = 0; r < 8; r++) {
            float f = sF[r][d];
            as[r] = fmaf(f, wsa, as[r]);
            bs[r] = fmaf(f, wsb, bs[r]);
            at[r] = fmaf(f, wta, at[r]);
            bt[r] = fmaf(f, wtb, bt[r]);
            ci[r] = fmaf(f, wib, ci[r]);
        }
    }
    #pragma unroll
    for (int r = 0; r < 8; r++) {
        int idx = (p0 + r)*H_ + h;
        g_As[idx]=as[r]; g_Bs[idx]=bs[r]; g_At[idx]=at[r]; g_Bt[idx]=bt[r]; g_Ci[idx]=ci[r];
    }
}

// ---------------- kernel C: interaction hidden, N-split + pipelined ---------
// CTA = (b,i) x n-half. Hi[j, n0+c] = relu((f_i.*f_j)@Wi1a + Ci_i + Ci_j + bi1)
// M=96, N=128, K=128. 384 threads, 12 warps = 3(m) x 4(n), warp tile 32x32.
__global__ void __launch_bounds__(384) bilinear_hi(
    const float* __restrict__ F, const float* __restrict__ bi1)
{
    __shared__ __align__(16) float sP[16][96 + 8];      // stride 104
    __shared__ __align__(16) float sW[16][128 + 8];     // stride 136
    __shared__ float sFi[D_], sCii[128], sBi1[128];

    int bi = blockIdx.x;
    int b  = bi / P_;
    int n0 = blockIdx.y * 128;
    int tid  = threadIdx.x;
    int warp = tid >> 5, lane = tid & 31;
    int wm = warp >> 2, wn = warp & 3;      // 3 x 4
    int grp = lane >> 2, thr = lane & 3;

    for (int t = tid; t < D_; t += 384) sFi[t] = F[bi*D_ + t];
    for (int t = tid; t < 128; t += 384) {
        sCii[t] = g_Ci[bi*H_ + n0 + t];
        sBi1[t] = bi1[n0 + t];
    }
    __syncthreads();

    int j_a = tid >> 2, k_a = (tid & 3) << 2;
    const float* rowF = F + (b*P_ + j_a) * D_;

    // sW loaders: 16 x 128 floats = 512 float4 over 384 threads -> 2 slots
    int w_k0 = tid >> 5,          w_n0 = (tid & 31) << 2;
    int w_k1 = (tid + 384) >> 5,  w_n1 = ((tid + 384) & 31) << 2;

    float acc[2][4][4];
    #pragma unroll
    for (int mt = 0; mt < 2; mt++)
        #pragma unroll
        for (int nt = 0; nt < 4; nt++)
            #pragma unroll
            for (int c = 0; c < 4; c++) acc[mt][nt][c] = 0.f;

    // prologue prefetch (d0 = 0)
    float4 vf  = *(const float4*)(rowF + k_a);
    float4 vw0 = *(const float4*)&g_Wi1t[w_k0*H_ + n0 + w_n0];
    float4 vw1;
    if (tid < 128) vw1 = *(const float4*)&g_Wi1t[w_k1*H_ + n0 + w_n1];

    for (int d0 = 0; d0 < D_; d0 += 16) {
        // build P tile from prefetched registers
        sP[k_a+0][j_a] = f2tf32(sFi[d0+k_a+0] * vf.x);
        sP[k_a+1][j_a] = f2tf32(sFi[d0+k_a+1] * vf.y);
        sP[k_a+2][j_a] = f2tf32(sFi[d0+k_a+2] * vf.z);
        sP[k_a+3][j_a] = f2tf32(sFi[d0+k_a+3] * vf.w);
        *(float4*)&sW[w_k0][w_n0] = vw0;
        if (tid < 128) *(float4*)&sW[w_k1][w_n1] = vw1;
        __syncthreads();

        // prefetch next stage while mma runs
        int dn = d0 + 16;
        if (dn < D_) {
            vf  = *(const float4*)(rowF + dn + k_a);
            vw0 = *(const float4*)&g_Wi1t[(dn + w_k0)*H_ + n0 + w_n0];
            if (tid < 128) vw1 = *(const float4*)&g_Wi1t[(dn + w_k1)*H_ + n0 + w_n1];
        }

        #pragma unroll
        for (int ks = 0; ks < 2; ks++) {
            int kb = ks * 8;
            uint32_t af[2][4], bf[4][2];
            #pragma unroll
            for (int mt = 0; mt < 2; mt++) {
                int row = wm*32 + mt*16 + grp;
                af[mt][0] = __float_as_uint(sP[kb + thr    ][row]);
                af[mt][1] = __float_as_uint(sP[kb + thr    ][row + 8]);
                af[mt][2] = __float_as_uint(sP[kb + thr + 4][row]);
                af[mt][3] = __float_as_uint(sP[kb + thr + 4][row + 8]);
            }
            #pragma unroll
            for (int nt = 0; nt < 4; nt++) {
                int col = wn*32 + nt*8 + grp;
                bf[nt][0] = __float_as_uint(sW[kb + thr    ][col]);
                bf[nt][1] = __float_as_uint(sW[kb + thr + 4][col]);
            }
            #pragma unroll
            for (int mt = 0; mt < 2; mt++)
                #pragma unroll
                for (int nt = 0; nt < 4; nt++)
                    asm volatile(
                        "mma.sync.aligned.m16n8k8.row.col.f32.tf32.tf32.f32 "
                        "{%0,%1,%2,%3}, {%4,%5,%6,%7}, {%8,%9}, {%0,%1,%2,%3};"
                        : "+f"(acc[mt][nt][0]), "+f"(acc[mt][nt][1]),
                          "+f"(acc[mt][nt][2]), "+f"(acc[mt][nt][3])
                        : "r"(af[mt][0]), "r"(af[mt][1]), "r"(af[mt][2]), "r"(af[mt][3]),
                          "r"(bf[nt][0]), "r"(bf[nt][1]));
        }
        __syncthreads();
    }

    // epilogue: + Ci_i + Ci_j + bi1, relu, tf32-round, store
    #pragma unroll
    for (int mt = 0; mt < 2; mt++) {
        #pragma unroll
        for (int half = 0; half < 2; half++) {
            int j = wm*32 + mt*16 + grp + half*8;
            const float* cij = g_Ci + (b*P_ + j)*H_ + n0;
            size_t obase = ((size_t)bi*P_ + j)*H_ + n0;
            #pragma unroll
            for (int nt = 0; nt < 4; nt++) {
                int col = wn*32 + nt*8 + thr*2;
                float2 v;
                v.x = f2tf32(fmaxf(acc[mt][nt][half*2+0] + sCii[col]   + cij[col]   + sBi1[col],   0.f));
                v.y = f2tf32(fmaxf(acc[mt][nt][half*2+1] + sCii[col+1] + cij[col+1] + sBi1[col+1], 0.f));
                *(float2*)&g_Hi[obase + col] = v;
            }
        }
    }
}

// ---------------- kernel D: fused GEMM (round-5 config: DN=128) -------------
// CTA = (b,i) x n-half. out[j,n] = sum_k relu(H[j,k]) * Wcat[k,n] + bias, * mask.
// M=96, N=128, K=768. 384 threads, 12 warps = 3(m) x 4(n), warp tile 32x32.
#define DN 128

__global__ void __launch_bounds__(384) gemm_fused(
    const float* __restrict__ dist, const float* __restrict__ mask,
    const float* __restrict__ Ws1,  float* __restrict__ out)
{
    __shared__ __align__(16) float sA[16][96 + 8];     // stride 104
    __shared__ __align__(16) float sB[16][DN + 8];     // stride 136
    __shared__ float sAsi[H_], sAti[H_], sW1c[H_];

    int bi = blockIdx.x;
    int b  = bi / P_;
    int n0 = blockIdx.y * DN;
    int tid  = threadIdx.x;
    int warp = tid >> 5, lane = tid & 31;
    int wm = warp >> 2, wn = warp & 3;      // 3 x 4
    int grp = lane >> 2, thr = lane & 3;

    for (int t = tid; t < H_; t += 384) {
        sAsi[t] = g_As[bi*H_ + t];
        sAti[t] = g_At[bi*H_ + t];
        sW1c[t] = Ws1[2*D_*H_ + t];        // Ws1 row 256 (distance)
    }
    __syncthreads();

    int j_a = tid >> 2, k_a = (tid & 3) << 2;
    const float* rowBs = g_Bs + (b*P_ + j_a)*H_;
    const float* rowBt = g_Bt + (b*P_ + j_a)*H_;
    const float* rowHi = g_Hi + ((size_t)bi*P_ + j_a)*H_;
    float dj = dist[bi*P_ + j_a];

    int sb_k0 = tid >> 5,          sb_n0 = (tid & 31) << 2;
    int sb_k1 = (tid + 384) >> 5,  sb_n1 = ((tid + 384) & 31) << 2;

    float acc[2][4][4];
    #pragma unroll
    for (int mt = 0; mt < 2; mt++)
        #pragma unroll
        for (int nt = 0; nt < 4; nt++)
            #pragma unroll
            for (int c = 0; c < 4; c++) acc[mt][nt][c] = 0.f;

    // prologue prefetch (k0 = 0, phase S)
    float4 va  = *(const float4*)(rowBs + k_a);
    float4 vb0 = *(const float4*)(&g_Wcat[sb_k0*H_ + n0 + sb_n0]);
    float4 vb1;
    if (tid < 128) vb1 = *(const float4*)(&g_Wcat[sb_k1*H_ + n0 + sb_n1]);

    for (int k0 = 0; k0 < K3; k0 += 16) {
        // build A tile
        float4 a;
        if (k0 < 256) {
            int kk = k0 + k_a;
            a.x = f2tf32(fmaxf(sAsi[kk+0] + va.x + dj*sW1c[kk+0], 0.f));
            a.y = f2tf32(fmaxf(sAsi[kk+1] + va.y + dj*sW1c[kk+1], 0.f));
            a.z = f2tf32(fmaxf(sAsi[kk+2] + va.z + dj*sW1c[kk+2], 0.f));
            a.w = f2tf32(fmaxf(sAsi[kk+3] + va.w + dj*sW1c[kk+3], 0.f));
        } else if (k0 < 512) {
            int kk = k0 - 256 + k_a;
            a.x = f2tf32(fmaxf(sAti[kk+0] + va.x, 0.f));
            a.y = f2tf32(fmaxf(sAti[kk+1] + va.y, 0.f));
            a.z = f2tf32(fmaxf(sAti[kk+2] + va.z, 0.f));
            a.w = f2tf32(fmaxf(sAti[kk+3] + va.w, 0.f));
        } else {
            a = va;   // g_Hi already relu'd + tf32-rounded
        }
        sA[k_a+0][j_a] = a.x; sA[k_a+1][j_a] = a.y;
        sA[k_a+2][j_a] = a.z; sA[k_a+3][j_a] = a.w;
        *(float4*)&sB[sb_k0][sb_n0] = vb0;
        if (tid < 128) *(float4*)&sB[sb_k1][sb_n1] = vb1;
        __syncthreads();

        // prefetch next stage while mma runs
        int kn = k0 + 16;
        if (kn < K3) {
            const float* src = (kn < 256) ? (rowBs + kn)
                             : (kn < 512) ? (rowBt + (kn - 256))
                                          : (rowHi + (kn - 512));
            va  = *(const float4*)(src + k_a);
            vb0 = *(const float4*)(&g_Wcat[(kn + sb_k0)*H_ + n0 + sb_n0]);
            if (tid < 128) vb1 = *(const float4*)(&g_Wcat[(kn + sb_k1)*H_ + n0 + sb_n1]);
        }

        #pragma unroll
        for (int ks = 0; ks < 2; ks++) {
            int kb = ks * 8;
            uint32_t af[2][4], bf[4][2];
            #pragma unroll
            for (int mt = 0; mt < 2; mt++) {
                int row = wm*32 + mt*16 + grp;
                af[mt][0] = __float_as_uint(sA[kb + thr    ][row]);
                af[mt][1] = __float_as_uint(sA[kb + thr    ][row + 8]);
                af[mt][2] = __float_as_uint(sA[kb + thr + 4][row]);
                af[mt][3] = __float_as_uint(sA[kb + thr + 4][row + 8]);
            }
            #pragma unroll
            for (int nt = 0; nt < 4; nt++) {
                int col = wn*32 + nt*8 + grp;
                bf[nt][0] = __float_as_uint(sB[kb + thr    ][col]);
                bf[nt][1] = __float_as_uint(sB[kb + thr + 4][col]);
            }
            #pragma unroll
            for (int mt = 0; mt < 2; mt++)
                #pragma unroll
                for (int nt = 0; nt < 4; nt++)
                    asm volatile(
                        "mma.sync.aligned.m16n8k8.row.col.f32.tf32.tf32.f32 "
                        "{%0,%1,%2,%3}, {%4,%5,%6,%7}, {%8,%9}, {%0,%1,%2,%3};"
                        : "+f"(acc[mt][nt][0]), "+f"(acc[mt][nt][1]),
                          "+f"(acc[mt][nt][2]), "+f"(acc[mt][nt][3])
                        : "r"(af[mt][0]), "r"(af[mt][1]), "r"(af[mt][2]), "r"(af[mt][3]),
                          "r"(bf[nt][0]), "r"(bf[nt][1]));
        }
        __syncthreads();
    }

    // epilogue
    float mi = mask[bi];
    #pragma unroll
    for (int mt = 0; mt < 2; mt++) {
        #pragma unroll
        for (int half = 0; half < 2; half++) {
            int j = wm*32 + mt*16 + grp + half*8;
            float mp = mi * mask[b*P_ + j];
            size_t obase = ((size_t)bi*P_ + j)*H_ + n0;
            #pragma unroll
            for (int nt = 0; nt < 4; nt++) {
                int col = wn*32 + nt*8 + thr*2;
                float2 v;
                v.x = (acc[mt][nt][half*2+0] + g_bias[n0 + col])     * mp;
                v.y = (acc[mt][nt][half*2+1] + g_bias[n0 + col + 1]) * mp;
                *(float2*)&out[obase + col] = v;
            }
        }
    }
}

// ---------------- launch --------------------------------------------------
extern "C" void kernel_launch(void* const* d_in, const int* in_sizes, int n_in,
                              void* d_out, int out_size)
{
    const float* F    = (const float*)d_in[0];
    const float* dist = (const float*)d_in[1];
    const float* mask = (const float*)d_in[2];
    const float* Ws1  = (const float*)d_in[3];
    const float* bs1  = (const float*)d_in[4];
    const float* Ws2  = (const float*)d_in[5];
    const float* bs2  = (const float*)d_in[6];
    const float* Wt1  = (const float*)d_in[7];
    const float* bt1  = (const float*)d_in[8];
    const float* Wt2  = (const float*)d_in[9];
    const float* bt2  = (const float*)d_in[10];
    const float* Wi1  = (const float*)d_in[11];
    const float* bi1  = (const float*)d_in[12];
    const float* Wi2  = (const float*)d_in[13];
    const float* bi2  = (const float*)d_in[14];
    const float* Wf   = (const float*)d_in[15];
    const float* bff  = (const float*)d_in[16];
    float* out = (float*)d_out;

    prep_weights<<<K3, 256>>>(Ws2, Wt2, Wi2, Wf, bs2, bt2, bi2, bff);
    prep_wi1<<<D_, 256>>>(Wi1);
    proj_points<<<NPTS/8, 256>>>(F, Ws1, Wt1, Wi1, bs1, bt1);
    bilinear_hi<<<dim3(NPTS, 2), 384>>>(F, bi1);
    gemm_fused<<<dim3(NPTS, H_ / DN), 384>>>(dist, mask, Ws1, out);
}

// round 10
// speedup vs baseline: 1.6607x; 1.4408x over previous
#include <cuda_runtime.h>
#include <cuda_fp16.h>
#include <cstdint>

#define B_    8
#define P_    96
#define D_    128
#define H_    256
#define NPTS  (B_*P_)          // 768
#define NPAIR (B_*P_*P_)       // 73728
#define K3    (3*H_)           // 768

// ---------------- device scratch ----------------
__device__ __align__(16) uint32_t g_WcatP[(K3/2)*H_];  // fused (W2@Wf), half2 k-pair packed: [kp][n]
__device__ __align__(16) float    g_bias[H_];
__device__ __align__(16) uint32_t g_Wi1P[(D_/2)*H_];   // Wi1 product-half, half2 k-pair packed
__device__ __align__(16) float    g_As[NPTS*H_];
__device__ __align__(16) float    g_Bs[NPTS*H_];
__device__ __align__(16) float    g_At[NPTS*H_];
__device__ __align__(16) float    g_Bt[NPTS*H_];
__device__ __align__(16) float    g_Ci[NPTS*H_];
__device__ __align__(16) __half   g_Hi[(size_t)NPAIR*H_];  // relu'd interaction hidden, fp16, 37.7MB

__device__ __forceinline__ uint32_t pack_h2(float lo, float hi) {
    __half2 h = __floats2half2_rn(lo, hi);
    return *(uint32_t*)&h;
}

// ---------------- kernel A: fuse layer-2 weights, half2 k-pair packed -------
__global__ void __launch_bounds__(256) prep_weights(
    const float* __restrict__ Ws2, const float* __restrict__ Wt2,
    const float* __restrict__ Wi2, const float* __restrict__ Wf,
    const float* __restrict__ bs2, const float* __restrict__ bt2,
    const float* __restrict__ bi2, const float* __restrict__ bff)
{
    int kp = blockIdx.x;           // 0..383 (k-pair)
    int h  = threadIdx.x;          // 0..255
    int k0 = 2*kp;
    int p  = k0 >> 8;              // branch (pairs never straddle the 256 boundary)
    int kk0 = k0 & 255, kk1 = kk0 + 1;
    const float* W2  = (p == 0) ? Ws2 : ((p == 1) ? Wt2 : Wi2);
    const float* Wfp = Wf + p * H_ * H_;
    float a0 = 0.f, a1 = 0.f;
    #pragma unroll 4
    for (int m = 0; m < H_; m++) {
        float w = Wfp[m*H_ + h];
        a0 = fmaf(W2[kk0*H_ + m], w, a0);
        a1 = fmaf(W2[kk1*H_ + m], w, a1);
    }
    g_WcatP[kp*H_ + h] = pack_h2(a0, a1);

    if (kp == 0) {
        float b = bff[h];
        for (int m = 0; m < H_; m++) {
            b = fmaf(bs2[m], Wf[m*H_ + h],          b);
            b = fmaf(bt2[m], Wf[(H_   + m)*H_ + h], b);
            b = fmaf(bi2[m], Wf[(2*H_ + m)*H_ + h], b);
        }
        g_bias[h] = b;
    }
}

// ---------------- kernel A2: pack Wi1 product-half to half2 k-pairs ---------
__global__ void __launch_bounds__(256) prep_wi1(const float* __restrict__ Wi1)
{
    int kp = blockIdx.x;           // 0..63
    int h  = threadIdx.x;          // 0..255
    g_Wi1P[kp*H_ + h] = pack_h2(Wi1[(2*kp)*H_ + h], Wi1[(2*kp+1)*H_ + h]);
}

// ---------------- kernel B: per-point projections (fp32) ----------------
__global__ void __launch_bounds__(256) proj_points(
    const float* __restrict__ F,   const float* __restrict__ Ws1,
    const float* __restrict__ Wt1, const float* __restrict__ Wi1,
    const float* __restrict__ bs1, const float* __restrict__ bt1)
{
    __shared__ __align__(16) float sF[8][D_];
    int p0 = blockIdx.x * 8;
    int h  = threadIdx.x;
    for (int t = h; t < 8*D_; t += 256) sF[t / D_][t % D_] = F[p0*D_ + t];
    __syncthreads();

    float as[8], bs[8], at[8], bt[8], ci[8];
    float b1 = bs1[h], b2 = bt1[h];
    #pragma unroll
    for (int r = 0; r < 8; r++) { as[r]=b1; bs[r]=0.f; at[r]=b2; bt[r]=0.f; ci[r]=0.f; }

    for (int d = 0; d < D_; d++) {
        float wsa = Ws1[d*H_ + h];
        float wsb = Ws1[(D_ + d)*H_ + h];
        float wta = Wt1[d*H_ + h];
        float wtb = Wt1[(D_ + d)*H_ + h];
        float wib = Wi1[(D_ + d)*H_ + h];
        #pragma unroll
        for (int r = 0; r < 8; r++) {
            float f = sF[r][d];
            as[r] = fmaf(f, wsa, as[r]);
            bs[r] = fmaf(f, wsb, bs[r]);
            at[r] = fmaf(f, wta, at[r]);
            bt[r] = fmaf(f, wtb, bt[r]);
            ci[r] = fmaf(f, wib, ci[r]);
        }
    }
    #pragma unroll
    for (int r = 0; r < 8; r++) {
        int idx = (p0 + r)*H_ + h;
        g_As[idx]=as[r]; g_Bs[idx]=bs[r]; g_At[idx]=at[r]; g_Bt[idx]=bt[r]; g_Ci[idx]=ci[r];
    }
}

// ---------------- kernel C: interaction hidden, fp16 mma --------------------
// CTA = (b,i) x n-half. Hi[j,n] = relu((f_i.*f_j)@Wi1a + Ci_i + Ci_j + bi1)
// M=96, N=128, K=128 (8 iters of k16). 384 thr, 12 warps 3(m)x4(n), tile 32x32.
__global__ void __launch_bounds__(384) bilinear_hi(
    const float* __restrict__ F, const float* __restrict__ bi1)
{
    __shared__ __align__(16) uint32_t sP[8][96 + 8];    // half2, stride 104 (mod32=8)
    __shared__ __align__(16) uint32_t sW[8][128 + 8];   // half2, stride 136 (mod32=8)
    __shared__ float sFi[D_], sCii[128], sBi1[128];

    int bi = blockIdx.x;
    int b  = bi / P_;
    int n0 = blockIdx.y * 128;
    int tid  = threadIdx.x;
    int warp = tid >> 5, lane = tid & 31;
    int wm = warp >> 2, wn = warp & 3;      // 3 x 4
    int grp = lane >> 2, thr = lane & 3;

    for (int t = tid; t < D_; t += 384) sFi[t] = F[bi*D_ + t];
    for (int t = tid; t < 128; t += 384) {
        sCii[t] = g_Ci[bi*H_ + n0 + t];
        sBi1[t] = bi1[n0 + t];
    }
    __syncthreads();

    int j_a = tid >> 2, k_a = (tid & 3) << 2;   // j 0..95, k offset {0,4,8,12}
    const float* rowF = F + (b*P_ + j_a) * D_;

    // sW loader: 8 rows x 128 uint32 = 256 uint4; threads 0..255, 1 each
    int w_row = tid >> 5, w_c = (tid & 31) << 2;
    bool w_act = tid < 256;

    float acc[2][4][4];
    #pragma unroll
    for (int mt = 0; mt < 2; mt++)
        #pragma unroll
        for (int nt = 0; nt < 4; nt++)
            #pragma unroll
            for (int c = 0; c < 4; c++) acc[mt][nt][c] = 0.f;

    // prologue prefetch (d0 = 0)
    float4 vf = *(const float4*)(rowF + k_a);
    uint4  vw;
    if (w_act) vw = *(const uint4*)&g_Wi1P[w_row*H_ + n0 + w_c];

    for (int d0 = 0; d0 < D_; d0 += 16) {
        int kp0 = k_a >> 1;
        sP[kp0    ][j_a] = pack_h2(sFi[d0+k_a+0]*vf.x, sFi[d0+k_a+1]*vf.y);
        sP[kp0 + 1][j_a] = pack_h2(sFi[d0+k_a+2]*vf.z, sFi[d0+k_a+3]*vf.w);
        if (w_act) *(uint4*)&sW[w_row][w_c] = vw;
        __syncthreads();

        int dn = d0 + 16;
        if (dn < D_) {
            vf = *(const float4*)(rowF + dn + k_a);
            if (w_act) vw = *(const uint4*)&g_Wi1P[((dn>>1) + w_row)*H_ + n0 + w_c];
        }

        uint32_t af[2][4], bf[4][2];
        #pragma unroll
        for (int mt = 0; mt < 2; mt++) {
            int row = wm*32 + mt*16 + grp;
            af[mt][0] = sP[thr    ][row];
            af[mt][1] = sP[thr    ][row + 8];
            af[mt][2] = sP[thr + 4][row];
            af[mt][3] = sP[thr + 4][row + 8];
        }
        #pragma unroll
        for (int nt = 0; nt < 4; nt++) {
            int col = wn*32 + nt*8 + grp;
            bf[nt][0] = sW[thr    ][col];
            bf[nt][1] = sW[thr + 4][col];
        }
        #pragma unroll
        for (int mt = 0; mt < 2; mt++)
            #pragma unroll
            for (int nt = 0; nt < 4; nt++)
                asm volatile(
                    "mma.sync.aligned.m16n8k16.row.col.f32.f16.f16.f32 "
                    "{%0,%1,%2,%3}, {%4,%5,%6,%7}, {%8,%9}, {%0,%1,%2,%3};"
                    : "+f"(acc[mt][nt][0]), "+f"(acc[mt][nt][1]),
                      "+f"(acc[mt][nt][2]), "+f"(acc[mt][nt][3])
                    : "r"(af[mt][0]), "r"(af[mt][1]), "r"(af[mt][2]), "r"(af[mt][3]),
                      "r"(bf[nt][0]), "r"(bf[nt][1]));
        __syncthreads();
    }

    // epilogue: + Ci_i + Ci_j + bi1, relu, fp16-round, store half2
    #pragma unroll
    for (int mt = 0; mt < 2; mt++) {
        #pragma unroll
        for (int half_ = 0; half_ < 2; half_++) {
            int j = wm*32 + mt*16 + grp + half_*8;
            const float* cij = g_Ci + (b*P_ + j)*H_ + n0;
            size_t obase = ((size_t)bi*P_ + j)*H_ + n0;
            #pragma unroll
            for (int nt = 0; nt < 4; nt++) {
                int col = wn*32 + nt*8 + thr*2;
                float vx = fmaxf(acc[mt][nt][half_*2+0] + sCii[col]   + cij[col]   + sBi1[col],   0.f);
                float vy = fmaxf(acc[mt][nt][half_*2+1] + sCii[col+1] + cij[col+1] + sBi1[col+1], 0.f);
                *(uint32_t*)&g_Hi[obase + col] = pack_h2(vx, vy);
            }
        }
    }
}

// ---------------- kernel D: fused GEMM, fp16 mma ----------------------------
// CTA = (b,i) x n-half. out[j,n] = sum_k relu(H[j,k]) * Wcat[k,n] + bias, * mask.
// M=96, N=128, K=768 (48 iters of k16). 384 thr, 12 warps 3x4, tile 32x32.
#define DN 128

__global__ void __launch_bounds__(384) gemm_fused(
    const float* __restrict__ dist, const float* __restrict__ mask,
    const float* __restrict__ Ws1,  float* __restrict__ out)
{
    __shared__ __align__(16) uint32_t sA[8][96 + 8];    // half2, stride 104
    __shared__ __align__(16) uint32_t sB[8][DN + 8];    // half2, stride 136
    __shared__ float sAsi[H_], sAti[H_], sW1c[H_];

    int bi = blockIdx.x;
    int b  = bi / P_;
    int n0 = blockIdx.y * DN;
    int tid  = threadIdx.x;
    int warp = tid >> 5, lane = tid & 31;
    int wm = warp >> 2, wn = warp & 3;      // 3 x 4
    int grp = lane >> 2, thr = lane & 3;

    for (int t = tid; t < H_; t += 384) {
        sAsi[t] = g_As[bi*H_ + t];
        sAti[t] = g_At[bi*H_ + t];
        sW1c[t] = Ws1[2*D_*H_ + t];        // Ws1 row 256 (distance)
    }
    __syncthreads();

    int j_a = tid >> 2, k_a = (tid & 3) << 2;
    const float*  rowBs = g_Bs + (b*P_ + j_a)*H_;
    const float*  rowBt = g_Bt + (b*P_ + j_a)*H_;
    const __half* rowHi = g_Hi + ((size_t)bi*P_ + j_a)*H_;
    float dj = dist[bi*P_ + j_a];

    // sB loader: 8 rows x 128 uint32 = 256 uint4; threads 0..255
    int w_row = tid >> 5, w_c = (tid & 31) << 2;
    bool w_act = tid < 256;

    float acc[2][4][4];
    #pragma unroll
    for (int mt = 0; mt < 2; mt++)
        #pragma unroll
        for (int nt = 0; nt < 4; nt++)
            #pragma unroll
            for (int c = 0; c < 4; c++) acc[mt][nt][c] = 0.f;

    // prologue prefetch (k0 = 0)
    float4 va = *(const float4*)(rowBs + k_a);
    uint2  vh;
    uint4  vb;
    if (w_act) vb = *(const uint4*)&g_WcatP[w_row*H_ + n0 + w_c];

    for (int k0 = 0; k0 < K3; k0 += 16) {
        int kp0 = k_a >> 1;
        if (k0 < 256) {
            int kk = k0 + k_a;
            sA[kp0  ][j_a] = pack_h2(fmaxf(sAsi[kk+0] + va.x + dj*sW1c[kk+0], 0.f),
                                     fmaxf(sAsi[kk+1] + va.y + dj*sW1c[kk+1], 0.f));
            sA[kp0+1][j_a] = pack_h2(fmaxf(sAsi[kk+2] + va.z + dj*sW1c[kk+2], 0.f),
                                     fmaxf(sAsi[kk+3] + va.w + dj*sW1c[kk+3], 0.f));
        } else if (k0 < 512) {
            int kk = k0 - 256 + k_a;
            sA[kp0  ][j_a] = pack_h2(fmaxf(sAti[kk+0] + va.x, 0.f),
                                     fmaxf(sAti[kk+1] + va.y, 0.f));
            sA[kp0+1][j_a] = pack_h2(fmaxf(sAti[kk+2] + va.z, 0.f),
                                     fmaxf(sAti[kk+3] + va.w, 0.f));
        } else {
            sA[kp0  ][j_a] = vh.x;   // g_Hi already relu'd fp16 pairs
            sA[kp0+1][j_a] = vh.y;
        }
        if (w_act) *(uint4*)&sB[w_row][w_c] = vb;
        __syncthreads();

        int kn = k0 + 16;
        if (kn < K3) {
            if (kn < 512) {
                const float* src = (kn < 256) ? (rowBs + kn) : (rowBt + (kn - 256));
                va = *(const float4*)(src + k_a);
            } else {
                vh = *(const uint2*)(rowHi + (kn - 512) + k_a);
            }
            if (w_act) vb = *(const uint4*)&g_WcatP[((kn>>1) + w_row)*H_ + n0 + w_c];
        }

        uint32_t af[2][4], bf[4][2];
        #pragma unroll
        for (int mt = 0; mt < 2; mt++) {
            int row = wm*32 + mt*16 + grp;
            af[mt][0] = sA[thr    ][row];
            af[mt][1] = sA[thr    ][row + 8];
            af[mt][2] = sA[thr + 4][row];
            af[mt][3] = sA[thr + 4][row + 8];
        }
        #pragma unroll
        for (int nt = 0; nt < 4; nt++) {
            int col = wn*32 + nt*8 + grp;
            bf[nt][0] = sB[thr    ][col];
            bf[nt][1] = sB[thr + 4][col];
        }
        #pragma unroll
        for (int mt = 0; mt < 2; mt++)
            #pragma unroll
            for (int nt = 0; nt < 4; nt++)
                asm volatile(
                    "mma.sync.aligned.m16n8k16.row.col.f32.f16.f16.f32 "
                    "{%0,%1,%2,%3}, {%4,%5,%6,%7}, {%8,%9}, {%0,%1,%2,%3};"
                    : "+f"(acc[mt][nt][0]), "+f"(acc[mt][nt][1]),
                      "+f"(acc[mt][nt][2]), "+f"(acc[mt][nt][3])
                    : "r"(af[mt][0]), "r"(af[mt][1]), "r"(af[mt][2]), "r"(af[mt][3]),
                      "r"(bf[nt][0]), "r"(bf[nt][1]));
        __syncthreads();
    }

    // epilogue
    float mi = mask[bi];
    #pragma unroll
    for (int mt = 0; mt < 2; mt++) {
        #pragma unroll
        for (int half_ = 0; half_ < 2; half_++) {
            int j = wm*32 + mt*16 + grp + half_*8;
            float mp = mi * mask[b*P_ + j];
            size_t obase = ((size_t)bi*P_ + j)*H_ + n0;
            #pragma unroll
            for (int nt = 0; nt < 4; nt++) {
                int col = wn*32 + nt*8 + thr*2;
                float2 v;
                v.x = (acc[mt][nt][half_*2+0] + g_bias[n0 + col])     * mp;
                v.y = (acc[mt][nt][half_*2+1] + g_bias[n0 + col + 1]) * mp;
                *(float2*)&out[obase + col] = v;
            }
        }
    }
}

// ---------------- launch --------------------------------------------------
extern "C" void kernel_launch(void* const* d_in, const int* in_sizes, int n_in,
                              void* d_out, int out_size)
{
    const float* F    = (const float*)d_in[0];
    const float* dist = (const float*)d_in[1];
    const float* mask = (const float*)d_in[2];
    const float* Ws1  = (const float*)d_in[3];
    const float* bs1  = (const float*)d_in[4];
    const float* Ws2  = (const float*)d_in[5];
    const float* bs2  = (const float*)d_in[6];
    const float* Wt1  = (const float*)d_in[7];
    const float* bt1  = (const float*)d_in[8];
    const float* Wt2  = (const float*)d_in[9];
    const float* bt2  = (const float*)d_in[10];
    const float* Wi1  = (const float*)d_in[11];
    const float* bi1  = (const float*)d_in[12];
    const float* Wi2  = (const float*)d_in[13];
    const float* bi2  = (const float*)d_in[14];
    const float* Wf   = (const float*)d_in[15];
    const float* bff  = (const float*)d_in[16];
    float* out = (float*)d_out;

    prep_weights<<<K3/2, 256>>>(Ws2, Wt2, Wi2, Wf, bs2, bt2, bi2, bff);
    prep_wi1<<<D_/2, 256>>>(Wi1);
    proj_points<<<NPTS/8, 256>>>(F, Ws1, Wt1, Wi1, bs1, bt1);
    bilinear_hi<<<dim3(NPTS, 2), 384>>>(F, bi1);
    gemm_fused<<<dim3(NPTS, H_ / DN), 384>>>(dist, mask, Ws1, out);
}

// round 12
// speedup vs baseline: 1.7993x; 1.0834x over previous
#include <cuda_runtime.h>
#include <cuda_fp16.h>
#include <cstdint>

#define B_    8
#define P_    96
#define D_    128
#define H_    256
#define NPTS  (B_*P_)          // 768
#define NPAIR (B_*P_*P_)       // 73728
#define K3    (3*H_)           // 768

// ---------------- device scratch ----------------
__device__ __align__(16) uint32_t g_WcatP[(K3/2)*H_];  // fused (W2@Wf), half2 k-pair packed: [kp][n]
__device__ __align__(16) float    g_bias[H_];
__device__ __align__(16) uint32_t g_Wi1P[(D_/2)*H_];   // Wi1 product-half, half2 k-pair packed
__device__ __align__(16) float    g_As[NPTS*H_];
__device__ __align__(16) float    g_Bs[NPTS*H_];
__device__ __align__(16) float    g_At[NPTS*H_];
__device__ __align__(16) float    g_Bt[NPTS*H_];
__device__ __align__(16) float    g_Ci[NPTS*H_];
__device__ __align__(16) __half   g_Hi[(size_t)NPAIR*H_];  // relu'd interaction hidden, fp16, 37.7MB

__device__ __forceinline__ uint32_t pack_h2(float lo, float hi) {
    __half2 h = __floats2half2_rn(lo, hi);
    return *(uint32_t*)&h;
}

// ---------------- combined prep: weights-fuse + wi1-pack + point-proj -------
__global__ void __launch_bounds__(256) prep_all(
    const float* __restrict__ Ws2, const float* __restrict__ Wt2,
    const float* __restrict__ Wi2, const float* __restrict__ Wf,
    const float* __restrict__ bs2, const float* __restrict__ bt2,
    const float* __restrict__ bi2, const float* __restrict__ bff,
    const float* __restrict__ F,   const float* __restrict__ Ws1,
    const float* __restrict__ Wt1, const float* __restrict__ Wi1,
    const float* __restrict__ bs1, const float* __restrict__ bt1)
{
    int bx = blockIdx.x;
    int h  = threadIdx.x;

    if (bx < K3/2) {
        // ---- fuse layer-2 with final projection, half2 k-pair pack ----
        int kp = bx;
        int k0 = 2*kp;
        int p  = k0 >> 8;
        int kk0 = k0 & 255, kk1 = kk0 + 1;
        const float* W2  = (p == 0) ? Ws2 : ((p == 1) ? Wt2 : Wi2);
        const float* Wfp = Wf + p * H_ * H_;
        float a0 = 0.f, a1 = 0.f;
        #pragma unroll 4
        for (int m = 0; m < H_; m++) {
            float w = Wfp[m*H_ + h];
            a0 = fmaf(W2[kk0*H_ + m], w, a0);
            a1 = fmaf(W2[kk1*H_ + m], w, a1);
        }
        g_WcatP[kp*H_ + h] = pack_h2(a0, a1);

        if (kp == 0) {
            float b = bff[h];
            for (int m = 0; m < H_; m++) {
                b = fmaf(bs2[m], Wf[m*H_ + h],          b);
                b = fmaf(bt2[m], Wf[(H_   + m)*H_ + h], b);
                b = fmaf(bi2[m], Wf[(2*H_ + m)*H_ + h], b);
            }
            g_bias[h] = b;
        }
    } else if (bx < K3/2 + D_/2) {
        // ---- pack Wi1 product-half to half2 k-pairs ----
        int kp = bx - K3/2;
        g_Wi1P[kp*H_ + h] = pack_h2(Wi1[(2*kp)*H_ + h], Wi1[(2*kp+1)*H_ + h]);
    } else {
        // ---- per-point projections ----
        __shared__ __align__(16) float sF[8][D_];
        int p0 = (bx - (K3/2 + D_/2)) * 8;
        for (int t = h; t < 8*D_; t += 256) sF[t / D_][t % D_] = F[p0*D_ + t];
        __syncthreads();

        float as[8], bs[8], at[8], bt[8], ci[8];
        float b1 = bs1[h], b2 = bt1[h];
        #pragma unroll
        for (int r = 0; r < 8; r++) { as[r]=b1; bs[r]=0.f; at[r]=b2; bt[r]=0.f; ci[r]=0.f; }

        for (int d = 0; d < D_; d++) {
            float wsa = Ws1[d*H_ + h];
            float wsb = Ws1[(D_ + d)*H_ + h];
            float wta = Wt1[d*H_ + h];
            float wtb = Wt1[(D_ + d)*H_ + h];
            float wib = Wi1[(D_ + d)*H_ + h];
            #pragma unroll
            for (int r = 0; r < 8; r++) {
                float f = sF[r][d];
                as[r] = fmaf(f, wsa, as[r]);
                bs[r] = fmaf(f, wsb, bs[r]);
                at[r] = fmaf(f, wta, at[r]);
                bt[r] = fmaf(f, wtb, bt[r]);
                ci[r] = fmaf(f, wib, ci[r]);
            }
        }
        #pragma unroll
        for (int r = 0; r < 8; r++) {
            int idx = (p0 + r)*H_ + h;
            g_As[idx]=as[r]; g_Bs[idx]=bs[r]; g_At[idx]=at[r]; g_Bt[idx]=bt[r]; g_Ci[idx]=ci[r];
        }
    }
}

// ---------------- kernel C: interaction hidden, fp16 mma, BK=32 -------------
// CTA = (b,i) x n-half. Hi[j,n] = relu((f_i.*f_j)@Wi1a + Ci_i + Ci_j + bi1)
// M=96, N=128, K=128 (4 iters of k32, double-buffered, 1 sync/iter).
__global__ void __launch_bounds__(384, 2) bilinear_hi(
    const float* __restrict__ F, const float* __restrict__ bi1)
{
    __shared__ __align__(16) uint32_t sP[2][16][96 + 8];    // half2, stride 104
    __shared__ __align__(16) uint32_t sW[2][16][128 + 8];   // half2, stride 136
    __shared__ float sFi[D_], sCii[128], sBi1[128];

    int bi = blockIdx.x;
    int b  = bi / P_;
    int n0 = blockIdx.y * 128;
    int tid  = threadIdx.x;
    int warp = tid >> 5, lane = tid & 31;
    int wm = warp >> 2, wn = warp & 3;      // 3 x 4
    int grp = lane >> 2, thr = lane & 3;

    for (int t = tid; t < D_; t += 384) sFi[t] = F[bi*D_ + t];
    for (int t = tid; t < 128; t += 384) {
        sCii[t] = g_Ci[bi*H_ + n0 + t];
        sBi1[t] = bi1[n0 + t];
    }
    __syncthreads();

    int j_a = tid >> 2, k_a = (tid & 3) << 3;   // j 0..95, k offset {0,8,16,24}
    const float* rowF = F + (b*P_ + j_a) * D_;

    // sW loader: 16 rows x 128 uint32 = 512 uint4; slot0 all threads, slot1 tid<128
    int w_r0 = tid >> 5,          w_c0 = (tid & 31) << 2;
    int w_r1 = (tid + 384) >> 5;  // 12..15
    bool w_act1 = tid < 128;

    float acc[2][4][4];
    #pragma unroll
    for (int mt = 0; mt < 2; mt++)
        #pragma unroll
        for (int nt = 0; nt < 4; nt++)
            #pragma unroll
            for (int c = 0; c < 4; c++) acc[mt][nt][c] = 0.f;

    // prologue prefetch (d0 = 0)
    float4 vf0 = *(const float4*)(rowF + k_a);
    float4 vf1 = *(const float4*)(rowF + k_a + 4);
    uint4  vw0 = *(const uint4*)&g_Wi1P[w_r0*H_ + n0 + w_c0];
    uint4  vw1;
    if (w_act1) vw1 = *(const uint4*)&g_Wi1P[w_r1*H_ + n0 + w_c0];

    for (int d0 = 0; d0 < D_; d0 += 32) {
        int buf = (d0 >> 5) & 1;
        int kp0 = k_a >> 1;                     // 4 k-pair rows per thread
        sP[buf][kp0+0][j_a] = pack_h2(sFi[d0+k_a+0]*vf0.x, sFi[d0+k_a+1]*vf0.y);
        sP[buf][kp0+1][j_a] = pack_h2(sFi[d0+k_a+2]*vf0.z, sFi[d0+k_a+3]*vf0.w);
        sP[buf][kp0+2][j_a] = pack_h2(sFi[d0+k_a+4]*vf1.x, sFi[d0+k_a+5]*vf1.y);
        sP[buf][kp0+3][j_a] = pack_h2(sFi[d0+k_a+6]*vf1.z, sFi[d0+k_a+7]*vf1.w);
        *(uint4*)&sW[buf][w_r0][w_c0] = vw0;
        if (w_act1) *(uint4*)&sW[buf][w_r1][w_c0] = vw1;
        __syncthreads();

        int dn = d0 + 32;
        if (dn < D_) {
            vf0 = *(const float4*)(rowF + dn + k_a);
            vf1 = *(const float4*)(rowF + dn + k_a + 4);
            vw0 = *(const uint4*)&g_Wi1P[((dn>>1) + w_r0)*H_ + n0 + w_c0];
            if (w_act1) vw1 = *(const uint4*)&g_Wi1P[((dn>>1) + w_r1)*H_ + n0 + w_c0];
        }

        #pragma unroll
        for (int s = 0; s < 2; s++) {
            int kb = s * 8;
            uint32_t af[2][4], bf[4][2];
            #pragma unroll
            for (int mt = 0; mt < 2; mt++) {
                int row = wm*32 + mt*16 + grp;
                af[mt][0] = sP[buf][kb + thr    ][row];
                af[mt][1] = sP[buf][kb + thr    ][row + 8];
                af[mt][2] = sP[buf][kb + thr + 4][row];
                af[mt][3] = sP[buf][kb + thr + 4][row + 8];
            }
            #pragma unroll
            for (int nt = 0; nt < 4; nt++) {
                int col = wn*32 + nt*8 + grp;
                bf[nt][0] = sW[buf][kb + thr    ][col];
                bf[nt][1] = sW[buf][kb + thr + 4][col];
            }
            #pragma unroll
            for (int mt = 0; mt < 2; mt++)
                #pragma unroll
                for (int nt = 0; nt < 4; nt++)
                    asm volatile(
                        "mma.sync.aligned.m16n8k16.row.col.f32.f16.f16.f32 "
                        "{%0,%1,%2,%3}, {%4,%5,%6,%7}, {%8,%9}, {%0,%1,%2,%3};"
                        : "+f"(acc[mt][nt][0]), "+f"(acc[mt][nt][1]),
                          "+f"(acc[mt][nt][2]), "+f"(acc[mt][nt][3])
                        : "r"(af[mt][0]), "r"(af[mt][1]), "r"(af[mt][2]), "r"(af[mt][3]),
                          "r"(bf[nt][0]), "r"(bf[nt][1]));
        }
    }

    // epilogue: + Ci_i + Ci_j + bi1, relu, fp16-round, store half2
    #pragma unroll
    for (int mt = 0; mt < 2; mt++) {
        #pragma unroll
        for (int half_ = 0; half_ < 2; half_++) {
            int j = wm*32 + mt*16 + grp + half_*8;
            const float* cij = g_Ci + (b*P_ + j)*H_ + n0;
            size_t obase = ((size_t)bi*P_ + j)*H_ + n0;
            #pragma unroll
            for (int nt = 0; nt < 4; nt++) {
                int col = wn*32 + nt*8 + thr*2;
                float vx = fmaxf(acc[mt][nt][half_*2+0] + sCii[col]   + cij[col]   + sBi1[col],   0.f);
                float vy = fmaxf(acc[mt][nt][half_*2+1] + sCii[col+1] + cij[col+1] + sBi1[col+1], 0.f);
                *(uint32_t*)&g_Hi[obase + col] = pack_h2(vx, vy);
            }
        }
    }
}

// ---------------- kernel D: fused GEMM, fp16 mma, BK=32 ---------------------
// CTA = (b,i) x n-half. out[j,n] = sum_k relu(H[j,k]) * Wcat[k,n] + bias, * mask.
// M=96, N=128, K=768 (24 iters of k32, double-buffered, 1 sync/iter).
#define DN 128

__global__ void __launch_bounds__(384, 2) gemm_fused(
    const float* __restrict__ dist, const float* __restrict__ mask,
    const float* __restrict__ Ws1,  float* __restrict__ out)
{
    __shared__ __align__(16) uint32_t sA[2][16][96 + 8];    // half2, stride 104
    __shared__ __align__(16) uint32_t sB[2][16][DN + 8];    // half2, stride 136
    __shared__ float sAsi[H_], sAti[H_], sW1c[H_];

    int bi = blockIdx.x;
    int b  = bi / P_;
    int n0 = blockIdx.y * DN;
    int tid  = threadIdx.x;
    int warp = tid >> 5, lane = tid & 31;
    int wm = warp >> 2, wn = warp & 3;      // 3 x 4
    int grp = lane >> 2, thr = lane & 3;

    for (int t = tid; t < H_; t += 384) {
        sAsi[t] = g_As[bi*H_ + t];
        sAti[t] = g_At[bi*H_ + t];
        sW1c[t] = Ws1[2*D_*H_ + t];        // Ws1 row 256 (distance)
    }
    __syncthreads();

    int j_a = tid >> 2, k_a = (tid & 3) << 3;   // j 0..95, k offset {0,8,16,24}
    const float*  rowBs = g_Bs + (b*P_ + j_a)*H_;
    const float*  rowBt = g_Bt + (b*P_ + j_a)*H_;
    const __half* rowHi = g_Hi + ((size_t)bi*P_ + j_a)*H_;
    float dj = dist[bi*P_ + j_a];

    int w_r0 = tid >> 5,          w_c0 = (tid & 31) << 2;
    int w_r1 = (tid + 384) >> 5;  // 12..15
    bool w_act1 = tid < 128;

    float acc[2][4][4];
    #pragma unroll
    for (int mt = 0; mt < 2; mt++)
        #pragma unroll
        for (int nt = 0; nt < 4; nt++)
            #pragma unroll
            for (int c = 0; c < 4; c++) acc[mt][nt][c] = 0.f;

    // prologue prefetch (k0 = 0). va0/va1 carry fp32 pairs for k<512; for the
    // Hi region va0 alone carries 8 halves (raw bits).
    float4 va0 = *(const float4*)(rowBs + k_a);
    float4 va1 = *(const float4*)(rowBs + k_a + 4);
    uint4  vb0 = *(const uint4*)&g_WcatP[w_r0*H_ + n0 + w_c0];
    uint4  vb1;
    if (w_act1) vb1 = *(const uint4*)&g_WcatP[w_r1*H_ + n0 + w_c0];

    for (int k0 = 0; k0 < K3; k0 += 32) {
        int buf = (k0 >> 5) & 1;
        int kp0 = k_a >> 1;
        if (k0 < 256) {
            int kk = k0 + k_a;
            sA[buf][kp0+0][j_a] = pack_h2(fmaxf(sAsi[kk+0] + va0.x + dj*sW1c[kk+0], 0.f),
                                          fmaxf(sAsi[kk+1] + va0.y + dj*sW1c[kk+1], 0.f));
            sA[buf][kp0+1][j_a] = pack_h2(fmaxf(sAsi[kk+2] + va0.z + dj*sW1c[kk+2], 0.f),
                                          fmaxf(sAsi[kk+3] + va0.w + dj*sW1c[kk+3], 0.f));
            sA[buf][kp0+2][j_a] = pack_h2(fmaxf(sAsi[kk+4] + va1.x + dj*sW1c[kk+4], 0.f),
                                          fmaxf(sAsi[kk+5] + va1.y + dj*sW1c[kk+5], 0.f));
            sA[buf][kp0+3][j_a] = pack_h2(fmaxf(sAsi[kk+6] + va1.z + dj*sW1c[kk+6], 0.f),
                                          fmaxf(sAsi[kk+7] + va1.w + dj*sW1c[kk+7], 0.f));
        } else if (k0 < 512) {
            int kk = k0 - 256 + k_a;
            sA[buf][kp0+0][j_a] = pack_h2(fmaxf(sAti[kk+0] + va0.x, 0.f),
                                          fmaxf(sAti[kk+1] + va0.y, 0.f));
            sA[buf][kp0+1][j_a] = pack_h2(fmaxf(sAti[kk+2] + va0.z, 0.f),
                                          fmaxf(sAti[kk+3] + va0.w, 0.f));
            sA[buf][kp0+2][j_a] = pack_h2(fmaxf(sAti[kk+4] + va1.x, 0.f),
                                          fmaxf(sAti[kk+5] + va1.y, 0.f));
            sA[buf][kp0+3][j_a] = pack_h2(fmaxf(sAti[kk+6] + va1.z, 0.f),
                                          fmaxf(sAti[kk+7] + va1.w, 0.f));
        } else {
            sA[buf][kp0+0][j_a] = __float_as_uint(va0.x);   // already relu'd fp16 pairs
            sA[buf][kp0+1][j_a] = __float_as_uint(va0.y);
            sA[buf][kp0+2][j_a] = __float_as_uint(va0.z);
            sA[buf][kp0+3][j_a] = __float_as_uint(va0.w);
        }
        *(uint4*)&sB[buf][w_r0][w_c0] = vb0;
        if (w_act1) *(uint4*)&sB[buf][w_r1][w_c0] = vb1;
        __syncthreads();

        int kn = k0 + 32;
        if (kn < K3) {
            if (kn < 512) {
                const float* src = (kn < 256) ? (rowBs + kn) : (rowBt + (kn - 256));
                va0 = *(const float4*)(src + k_a);
                va1 = *(const float4*)(src + k_a + 4);
            } else {
                va0 = *(const float4*)(const void*)(rowHi + (kn - 512) + k_a);
            }
            vb0 = *(const uint4*)&g_WcatP[((kn>>1) + w_r0)*H_ + n0 + w_c0];
            if (w_act1) vb1 = *(const uint4*)&g_WcatP[((kn>>1) + w_r1)*H_ + n0 + w_c0];
        }

        #pragma unroll
        for (int s = 0; s < 2; s++) {
            int kb = s * 8;
            uint32_t af[2][4], bf[4][2];
            #pragma unroll
            for (int mt = 0; mt < 2; mt++) {
                int row = wm*32 + mt*16 + grp;
                af[mt][0] = sA[buf][kb + thr    ][row];
                af[mt][1] = sA[buf][kb + thr    ][row + 8];
                af[mt][2] = sA[buf][kb + thr + 4][row];
                af[mt][3] = sA[buf][kb + thr + 4][row + 8];
            }
            #pragma unroll
            for (int nt = 0; nt < 4; nt++) {
                int col = wn*32 + nt*8 + grp;
                bf[nt][0] = sB[buf][kb + thr    ][col];
                bf[nt][1] = sB[buf][kb + thr + 4][col];
            }
            #pragma unroll
            for (int mt = 0; mt < 2; mt++)
                #pragma unroll
                for (int nt = 0; nt < 4; nt++)
                    asm volatile(
                        "mma.sync.aligned.m16n8k16.row.col.f32.f16.f16.f32 "
                        "{%0,%1,%2,%3}, {%4,%5,%6,%7}, {%8,%9}, {%0,%1,%2,%3};"
                        : "+f"(acc[mt][nt][0]), "+f"(acc[mt][nt][1]),
                          "+f"(acc[mt][nt][2]), "+f"(acc[mt][nt][3])
                        : "r"(af[mt][0]), "r"(af[mt][1]), "r"(af[mt][2]), "r"(af[mt][3]),
                          "r"(bf[nt][0]), "r"(bf[nt][1]));
        }
    }

    // epilogue
    float mi = mask[bi];
    #pragma unroll
    for (int mt = 0; mt < 2; mt++) {
        #pragma unroll
        for (int half_ = 0; half_ < 2; half_++) {
            int j = wm*32 + mt*16 + grp + half_*8;
            float mp = mi * mask[b*P_ + j];
            size_t obase = ((size_t)bi*P_ + j)*H_ + n0;
            #pragma unroll
            for (int nt = 0; nt < 4; nt++) {
                int col = wn*32 + nt*8 + thr*2;
                float2 v;
                v.x = (acc[mt][nt][half_*2+0] + g_bias[n0 + col])     * mp;
                v.y = (acc[mt][nt][half_*2+1] + g_bias[n0 + col + 1]) * mp;
                *(float2*)&out[obase + col] = v;
            }
        }
    }
}

// ---------------- launch --------------------------------------------------
extern "C" void kernel_launch(void* const* d_in, const int* in_sizes, int n_in,
                              void* d_out, int out_size)
{
    const float* F    = (const float*)d_in[0];
    const float* dist = (const float*)d_in[1];
    const float* mask = (const float*)d_in[2];
    const float* Ws1  = (const float*)d_in[3];
    const float* bs1  = (const float*)d_in[4];
    const float* Ws2  = (const float*)d_in[5];
    const float* bs2  = (const float*)d_in[6];
    const float* Wt1  = (const float*)d_in[7];
    const float* bt1  = (const float*)d_in[8];
    const float* Wt2  = (const float*)d_in[9];
    const float* bt2  = (const float*)d_in[10];
    const float* Wi1  = (const float*)d_in[11];
    const float* bi1  = (const float*)d_in[12];
    const float* Wi2  = (const float*)d_in[13];
    const float* bi2  = (const float*)d_in[14];
    const float* Wf   = (const float*)d_in[15];
    const float* bff  = (const float*)d_in[16];
    float* out = (float*)d_out;

    prep_all<<<K3/2 + D_/2 + NPTS/8, 256>>>(Ws2, Wt2, Wi2, Wf, bs2, bt2, bi2, bff,
                                            F, Ws1, Wt1, Wi1, bs1, bt1);
    bilinear_hi<<<dim3(NPTS, 2), 384>>>(F, bi1);
    gemm_fused<<<dim3(NPTS, H_ / DN), 384>>>(dist, mask, Ws1, out);
}